// round 7
// baseline (speedup 1.0000x reference)
#include <cuda_runtime.h>
#include <cuda_bf16.h>
#include <math.h>
#include <stdint.h>

#define BQ   16
#define TT   1000
#define MEL  80
#define HID  512
#define NCLS 64
#define NROW (BQ*TT)

#define CLN  8       // CTAs per cluster
#define NCTA 128     // 16 clusters (one per batch element) * 8 CTAs

#define CROWF 528u                  // fp32 C1 row stride in floats (2112 B, conflict-free)
#define WROWB 1088u                 // bf16 W1 row stride in bytes  (conflict-free)
#define CMATB (64u*CROWF*4u)        // 135168 B
#define WMATB (64u*WROWB)           // 69632 B
#define DYNSM (CMATB + WMATB)       // 204800 B

// ---------------- scratch (static device globals; no allocations) ----------------
__device__ float g_be0[NROW*HID];
__device__ float g_be1[NROW*HID];
__device__ float g_h1 [NROW*HID];
__device__ float g_xs1[NROW];

__device__ __forceinline__ float sigm(float x){ return 1.0f/(1.0f+expf(-x)); }

__device__ __forceinline__ uint32_t smem_u32(const void* p){
  uint32_t a;
  asm("{ .reg .u64 t; cvta.to.shared.u64 t, %1; cvt.u32.u64 %0, t; }" : "=r"(a) : "l"(p));
  return a;
}
__device__ __forceinline__ void dsmem_st4(uint32_t laddr, uint32_t rnk, float4 v){
  uint32_t ra;
  asm volatile("mapa.shared::cluster.u32 %0, %1, %2;" : "=r"(ra) : "r"(laddr), "r"(rnk));
  asm volatile("st.shared::cluster.v4.f32 [%0], {%1,%2,%3,%4};"
               :: "r"(ra), "f"(v.x), "f"(v.y), "f"(v.z), "f"(v.w) : "memory");
}
__device__ __forceinline__ void dsmem_st1(uint32_t laddr, uint32_t rnk, float v){
  uint32_t ra;
  asm volatile("mapa.shared::cluster.u32 %0, %1, %2;" : "=r"(ra) : "r"(laddr), "r"(rnk));
  asm volatile("st.shared::cluster.f32 [%0], %1;" :: "r"(ra), "f"(v) : "memory");
}
#define CLUSTER_SYNC() do{ \
  asm volatile("barrier.cluster.arrive.aligned;" ::: "memory"); \
  asm volatile("barrier.cluster.wait.aligned;"  ::: "memory"); }while(0)

// ---------------- be0 = clip(feats/||feats||) @ B0^T ; xs1 = ||be0|| ----------------
__global__ __launch_bounds__(256) void k_be0(const float* __restrict__ feats,
                                             const float* __restrict__ B0){
  __shared__ float xn[16][MEL];
  __shared__ float snorm[16];
  __shared__ float sxs[16];
  int tid = threadIdx.x;
  int row0 = blockIdx.x*16;
  for (int i=tid;i<16*MEL;i+=256)
    xn[i/MEL][i%MEL] = feats[row0*MEL + i];
  __syncthreads();
  if (tid<16){
    float s=0.f;
    #pragma unroll
    for (int k=0;k<MEL;k++){ float v=xn[tid][k]; s+=v*v; }
    sxs[tid]=fmaxf(sqrtf(s),1e-6f);
    snorm[tid]=0.f;
  }
  __syncthreads();
  for (int i=tid;i<16*MEL;i+=256){
    int r=i/MEL;
    float v = xn[r][i%MEL]/sxs[r];
    xn[r][i%MEL] = fminf(fmaxf(v,-1.f),1.f);
  }
  __syncthreads();
  int n0=tid, n1=tid+256;
  float a0[16], a1_[16];
  #pragma unroll
  for (int r=0;r<16;r++){ a0[r]=0.f; a1_[r]=0.f; }
  for (int k=0;k<MEL;k+=4){
    float4 w0 = *(const float4*)&B0[n0*MEL+k];
    float4 w1 = *(const float4*)&B0[n1*MEL+k];
    #pragma unroll
    for (int r=0;r<16;r++){
      float4 x = *(const float4*)&xn[r][k];
      a0 [r] += w0.x*x.x + w0.y*x.y + w0.z*x.z + w0.w*x.w;
      a1_[r] += w1.x*x.x + w1.y*x.y + w1.z*x.z + w1.w*x.w;
    }
  }
  #pragma unroll
  for (int r=0;r<16;r++){
    g_be0[(row0+r)*HID+n0]=a0[r];
    g_be0[(row0+r)*HID+n1]=a1_[r];
    atomicAdd(&snorm[r], a0[r]*a0[r] + a1_[r]*a1_[r]);
  }
  __syncthreads();
  if (tid<16) g_xs1[row0+tid] = fmaxf(sqrtf(snorm[tid]),1e-6f);
}

// ---------------- be1 = clip(be0/xs1) @ B1^T ----------------
__global__ __launch_bounds__(256) void k_be1(const float* __restrict__ B1){
  __shared__ float xn[16][HID];
  __shared__ float sxs[16];
  int tid=threadIdx.x;
  int row0=blockIdx.x*16;
  if (tid<16) sxs[tid]=g_xs1[row0+tid];
  __syncthreads();
  for (int i=tid;i<16*HID;i+=256){
    int r=i>>9;
    float v = g_be0[row0*HID + i]/sxs[r];
    xn[r][i&511] = fminf(fmaxf(v,-1.f),1.f);
  }
  __syncthreads();
  int n0=tid, n1=tid+256;
  float a0[16], a1_[16];
  #pragma unroll
  for (int r=0;r<16;r++){ a0[r]=0.f; a1_[r]=0.f; }
  for (int k=0;k<HID;k+=4){
    float4 w0 = *(const float4*)&B1[n0*HID+k];
    float4 w1 = *(const float4*)&B1[n1*HID+k];
    #pragma unroll
    for (int r=0;r<16;r++){
      float4 x = *(const float4*)&xn[r][k];
      a0 [r] += w0.x*x.x + w0.y*x.y + w0.z*x.z + w0.w*x.w;
      a1_[r] += w1.x*x.x + w1.y*x.y + w1.z*x.z + w1.w*x.w;
    }
  }
  #pragma unroll
  for (int r=0;r<16;r++){
    g_be1[(row0+r)*HID+n0]=a0[r];
    g_be1[(row0+r)*HID+n1]=a1_[r];
  }
}

// ---------------- serial recurrence: 1 batch / 8-CTA cluster, 16 clusters ----------
// CTA `rank` owns rows [rank*64, rank*64+64). C1 slice fp32 in smem, W1 slice bf16.
// h/err exchanged by DSMEM push (plain layout); thread = (row, kq:0..3) so all rows
// broadcast-read the same x addresses.
__global__ __launch_bounds__(256,1) __cluster_dims__(CLN,1,1)
void k_serial(const float* __restrict__ C1, const float* __restrict__ W1,
              const float* __restrict__ a1, const float* __restrict__ tau,
              const float* __restrict__ gam){
  extern __shared__ __align__(16) uint8_t dynsm[];
  float*   wsmC = (float*)dynsm;                 // [64][CROWF] fp32
  uint8_t* wsmW = dynsm + CMATB;                 // [64][WROWB] bf16

  __shared__ __align__(16) float hbuf[HID];      // full h   (remote-written)
  __shared__ __align__(16) float ebuf[HID];      // full err (remote-written)
  __shared__ __align__(16) float estage[64];
  __shared__ __align__(16) float hstage[64];
  __shared__ float pout[64];
  __shared__ float narr[CLN];
  __shared__ float normloc;
  __shared__ float sa[64];

  const int tid  = threadIdx.x;
  const int rank = blockIdx.x & (CLN-1);
  const int b    = blockIdx.x >> 3;              // batch element for this cluster
  const int row  = tid >> 2, kq = tid & 3;
  const float tauv = __ldg(&tau[0]), gamv = __ldg(&gam[0]);

  // -------- prologue: stage weight slices (C1 fp32, W1 bf16) --------
  for (int i=tid; i<64*128; i+=256){
    int r=i>>7, q=i&127;                               // q = float4 index in row
    float4 vc = __ldg((const float4*)&C1[(rank*64+r)*HID + q*4]);
    float4 vw = __ldg((const float4*)&W1[(rank*64+r)*HID + q*4]);
    *(float4*)&wsmC[(unsigned)r*CROWF + (unsigned)q*4u] = vc;
    __nv_bfloat162 w0 = __floats2bfloat162_rn(vw.x, vw.y);
    __nv_bfloat162 w1 = __floats2bfloat162_rn(vw.z, vw.w);
    uint2 uw; uw.x = *(uint32_t*)&w0; uw.y = *(uint32_t*)&w1;
    *(uint2*)(wsmW + (unsigned)r*WROWB + (unsigned)q*8u) = uw;
  }
  for (int i=tid;i<HID;i+=256) hbuf[i]=0.f;
  if (tid==0) normloc=0.f;
  if (tid<64) sa[tid] = sigm(__ldg(&a1[rank*64+tid]));
  __syncthreads();

  const uint32_t a_ebuf = smem_u32(&ebuf[0]);
  const uint32_t a_hbuf = smem_u32(&hbuf[0]);
  const uint32_t a_narr = smem_u32(&narr[0]);

  const int dest = tid >> 4, chunk = tid & 15;         // push mapping (tid<128)
  const uint32_t x_off = (uint32_t)(rank*16 + chunk)*16u;
  const float* wrC = &wsmC[(unsigned)row*CROWF + (unsigned)kq*4u];
  const uint8_t* wrW = wsmW + (unsigned)row*WROWB + (unsigned)kq*16u;

  for (int t=0;t<TT;t++){
    // prefetch per-step scalars (consumed ~1000 cyc later)
    float xsv=1.f, be0v=0.f, be1v=0.f;
    if (tid<64){
      xsv  = __ldg(&g_xs1[b*TT+t]);
      be0v = __ldg(&g_be0[(b*TT+t)*HID + rank*64 + tid]);
      be1v = __ldg(&g_be1[(b*TT+t)*HID + rank*64 + tid]);
    }

    // ======== phase 1: p = h @ C1^T (fp32), err, norm ========
    {
      float a0=0.f,a1_=0.f,a2=0.f,a3=0.f;
      #pragma unroll
      for (int m=0;m<32;m+=4){
        #pragma unroll
        for (int j=0;j<4;j++){
          int q = (m+j)*4 + kq;                        // float4 group index
          float4 w = *(const float4*)(wrC + (unsigned)(m+j)*16u);
          float4 x = *(const float4*)&hbuf[q*4];
          float* ap = (j==0)?&a0:(j==1)?&a1_:(j==2)?&a2:&a3;
          *ap += w.x*x.x + w.y*x.y + w.z*x.z + w.w*x.w;
        }
      }
      float s = (a0+a1_)+(a2+a3);
      s += __shfl_down_sync(0xffffffffu, s, 2);
      s += __shfl_down_sync(0xffffffffu, s, 1);
      if (kq==0) pout[row]=s;
    }
    __syncthreads();
    if (tid<64){
      float p = tanhf(pout[tid]) * xsv;
      float e = be0v - p;
      estage[tid] = e;
      float q = e*e;
      #pragma unroll
      for (int off=16; off; off>>=1) q += __shfl_xor_sync(0xffffffffu,q,off);
      if ((tid&31)==0) atomicAdd(&normloc, q);
    }
    __syncthreads();
    if (tid<128){
      float4 v = ((const float4*)estage)[chunk];
      dsmem_st4(a_ebuf + x_off, (uint32_t)dest, v);
    } else if (tid<136){
      dsmem_st1(a_narr + (uint32_t)(rank*4), (uint32_t)(tid-128), normloc);
    }
    CLUSTER_SYNC();

    // ======== phase 2: surprise, ee = err @ W1^T (bf16), h update ========
    {
      float a0=0.f,a1_=0.f,a2=0.f,a3=0.f;
      #pragma unroll
      for (int m=0;m<16;m+=4){
        #pragma unroll
        for (int j=0;j<4;j++){
          int q = (m+j)*4 + kq;                        // uint4 (8 bf16) index
          uint4 w = *(const uint4*)(wrW + (unsigned)(m+j)*64u);
          float4 x0 = *(const float4*)&ebuf[q*8];
          float4 x1 = *(const float4*)&ebuf[q*8+4];
          float w0=__uint_as_float(w.x<<16), w1=__uint_as_float(w.x&0xffff0000u);
          float w2=__uint_as_float(w.y<<16), w3=__uint_as_float(w.y&0xffff0000u);
          float w4=__uint_as_float(w.z<<16), w5=__uint_as_float(w.z&0xffff0000u);
          float w6=__uint_as_float(w.w<<16), w7=__uint_as_float(w.w&0xffff0000u);
          float* ap = (j==0)?&a0:(j==1)?&a1_:(j==2)?&a2:&a3;
          *ap += w0*x0.x + w1*x0.y + w2*x0.z + w3*x0.w
               + w4*x1.x + w5*x1.y + w6*x1.z + w7*x1.w;
        }
      }
      float s = (a0+a1_)+(a2+a3);
      s += __shfl_down_sync(0xffffffffu, s, 2);
      s += __shfl_down_sync(0xffffffffu, s, 1);
      if (kq==0) pout[row]=s;
    }
    __syncthreads();
    if (tid<64){
      float n2 = (narr[0]+narr[1])+(narr[2]+narr[3])
               + (narr[4]+narr[5])+(narr[6]+narr[7]);
      float rel = fminf(sqrtf(n2)/xsv, 4.0f);
      float s = sigm((rel - tauv)/gamv);
      float hold = hbuf[rank*64+tid];
      float ih = 0.2f*hold + 0.6f*be1v + 0.2f*s*pout[tid];
      float g = s*sa[tid];
      float hn = hold*(1.f-g) + tanhf(ih)*g;
      hstage[tid] = hn;
      g_h1[(b*TT+t)*HID + rank*64 + tid] = hn;
    } else if (tid==64){
      normloc = 0.f;                                   // reset for next step
    }
    __syncthreads();
    if (tid<128){
      float4 v = ((const float4*)hstage)[chunk];
      dsmem_st4(a_hbuf + x_off, (uint32_t)dest, v);
    }
    CLUSTER_SYNC();
  }
}

// ---------------- head: out = [h1, be1] @ head_w^T + head_b ----------------
__global__ __launch_bounds__(256) void k_head(const float* __restrict__ hw,
                                              const float* __restrict__ hb,
                                              float* __restrict__ out){
  __shared__ float sh[8*1024];
  __shared__ float sred[4*8*64];
  int tid=threadIdx.x;
  int row0=blockIdx.x*8;
  for (int i=tid;i<8*1024;i+=256){
    int r=i>>10, j=i&1023;
    sh[i] = (j<512)? g_h1[(row0+r)*HID+j] : g_be1[(row0+r)*HID+(j-512)];
  }
  __syncthreads();
  int c=tid&63, q=tid>>6;
  float acc[8];
  #pragma unroll
  for (int r=0;r<8;r++) acc[r]=0.f;
  for (int k=q*256;k<q*256+256;k+=4){
    float4 w = *(const float4*)&hw[c*1024+k];
    #pragma unroll
    for (int r=0;r<8;r++){
      float4 x = *(const float4*)&sh[r*1024+k];
      acc[r] += w.x*x.x + w.y*x.y + w.z*x.z + w.w*x.w;
    }
  }
  #pragma unroll
  for (int r=0;r<8;r++) sred[(q*8+r)*64+c]=acc[r];
  __syncthreads();
  for (int i=tid;i<8*64;i+=256){
    int r=i>>6, cc=i&63;
    out[(row0+r)*NCLS+cc] = sred[r*64+cc] + sred[(8+r)*64+cc]
                          + sred[(16+r)*64+cc] + sred[(24+r)*64+cc] + __ldg(&hb[cc]);
  }
}

// ---------------- launch ----------------
extern "C" void kernel_launch(void* const* d_in, const int* in_sizes, int n_in,
                              void* d_out, int out_size){
  const float* feats=(const float*)d_in[0];
  const float* B0  =(const float*)d_in[2];
  const float* C1  =(const float*)d_in[7];
  const float* B1  =(const float*)d_in[8];
  const float* W1  =(const float*)d_in[9];
  const float* a1  =(const float*)d_in[10];
  const float* tau1=(const float*)d_in[11];
  const float* gam1=(const float*)d_in[12];
  const float* hw  =(const float*)d_in[13];
  const float* hb  =(const float*)d_in[14];
  float* out=(float*)d_out;

  static int smem_set = 0;
  if (!smem_set){
    cudaFuncSetAttribute(k_serial, cudaFuncAttributeMaxDynamicSharedMemorySize, DYNSM);
    smem_set = 1;
  }

  k_be0   <<<NROW/16,256>>>(feats,B0);
  k_be1   <<<NROW/16,256>>>(B1);
  k_serial<<<NCTA,256,DYNSM>>>(C1,W1,a1,tau1,gam1);
  k_head  <<<NROW/8,256>>>(hw,hb,out);
}

// round 8
// speedup vs baseline: 1.6652x; 1.6652x over previous
#include <cuda_runtime.h>
#include <cuda_bf16.h>
#include <math.h>
#include <stdint.h>

#define BQ   16
#define TT   1000
#define MEL  80
#define HID  512
#define NCLS 64
#define NROW (BQ*TT)

#define CLN  8       // CTAs per cluster  (8 clusters x 8 CTAs = 64 -- proven placement)
#define NCTA 64
#define BPC  2       // batch elements per cluster

#define WROWB 1040u                 // bf16 row stride bytes (1024 + 16 pad)
#define WMATB (64u*WROWB)           // 66560 B per matrix slice
#define DYNSM (2u*WMATB)            // 133120 B

// ---------------- scratch (static device globals; no allocations) ----------------
__device__ float g_be0[NROW*HID];
__device__ float g_be1[NROW*HID];
__device__ float g_h1 [NROW*HID];
__device__ float g_xs1[NROW];

__device__ __forceinline__ float sigm(float x){ return 1.0f/(1.0f+expf(-x)); }

__device__ __forceinline__ uint32_t smem_u32(const void* p){
  uint32_t a;
  asm("{ .reg .u64 t; cvta.to.shared.u64 t, %1; cvt.u32.u64 %0, t; }" : "=r"(a) : "l"(p));
  return a;
}
__device__ __forceinline__ void dsmem_st4(uint32_t laddr, uint32_t rnk, float4 v){
  uint32_t ra;
  asm volatile("mapa.shared::cluster.u32 %0, %1, %2;" : "=r"(ra) : "r"(laddr), "r"(rnk));
  asm volatile("st.shared::cluster.v4.f32 [%0], {%1,%2,%3,%4};"
               :: "r"(ra), "f"(v.x), "f"(v.y), "f"(v.z), "f"(v.w) : "memory");
}
__device__ __forceinline__ void dsmem_st1(uint32_t laddr, uint32_t rnk, float v){
  uint32_t ra;
  asm volatile("mapa.shared::cluster.u32 %0, %1, %2;" : "=r"(ra) : "r"(laddr), "r"(rnk));
  asm volatile("st.shared::cluster.f32 [%0], %1;" :: "r"(ra), "f"(v) : "memory");
}
#define CLUSTER_SYNC() do{ \
  asm volatile("barrier.cluster.arrive.aligned;" ::: "memory"); \
  asm volatile("barrier.cluster.wait.aligned;"  ::: "memory"); }while(0)

// packed f32x2 helpers (sm_103a)
__device__ __forceinline__ unsigned long long bpack(unsigned lo, unsigned hi){
  unsigned long long r;
  asm("mov.b64 %0, {%1,%2};" : "=l"(r) : "r"(lo), "r"(hi));
  return r;
}
__device__ __forceinline__ void ffma2(unsigned long long& a, unsigned long long w,
                                      unsigned long long x){
  asm("fma.rn.f32x2 %0, %1, %2, %0;" : "+l"(a) : "l"(w), "l"(x));
}
__device__ __forceinline__ float hsum2(unsigned long long a){
  return __uint_as_float((unsigned)(a & 0xffffffffu)) +
         __uint_as_float((unsigned)(a >> 32));
}

// ---------------- be0 = clip(feats/||feats||) @ B0^T ; xs1 = ||be0|| ----------------
__global__ __launch_bounds__(256) void k_be0(const float* __restrict__ feats,
                                             const float* __restrict__ B0){
  __shared__ float xn[16][MEL];
  __shared__ float snorm[16];
  __shared__ float sxs[16];
  int tid = threadIdx.x;
  int row0 = blockIdx.x*16;
  for (int i=tid;i<16*MEL;i+=256)
    xn[i/MEL][i%MEL] = feats[row0*MEL + i];
  __syncthreads();
  if (tid<16){
    float s=0.f;
    #pragma unroll
    for (int k=0;k<MEL;k++){ float v=xn[tid][k]; s+=v*v; }
    sxs[tid]=fmaxf(sqrtf(s),1e-6f);
    snorm[tid]=0.f;
  }
  __syncthreads();
  for (int i=tid;i<16*MEL;i+=256){
    int r=i/MEL;
    float v = xn[r][i%MEL]/sxs[r];
    xn[r][i%MEL] = fminf(fmaxf(v,-1.f),1.f);
  }
  __syncthreads();
  int n0=tid, n1=tid+256;
  float a0[16], a1_[16];
  #pragma unroll
  for (int r=0;r<16;r++){ a0[r]=0.f; a1_[r]=0.f; }
  for (int k=0;k<MEL;k+=4){
    float4 w0 = *(const float4*)&B0[n0*MEL+k];
    float4 w1 = *(const float4*)&B0[n1*MEL+k];
    #pragma unroll
    for (int r=0;r<16;r++){
      float4 x = *(const float4*)&xn[r][k];
      a0 [r] += w0.x*x.x + w0.y*x.y + w0.z*x.z + w0.w*x.w;
      a1_[r] += w1.x*x.x + w1.y*x.y + w1.z*x.z + w1.w*x.w;
    }
  }
  #pragma unroll
  for (int r=0;r<16;r++){
    g_be0[(row0+r)*HID+n0]=a0[r];
    g_be0[(row0+r)*HID+n1]=a1_[r];
    atomicAdd(&snorm[r], a0[r]*a0[r] + a1_[r]*a1_[r]);
  }
  __syncthreads();
  if (tid<16) g_xs1[row0+tid] = fmaxf(sqrtf(snorm[tid]),1e-6f);
}

// ---------------- be1 = clip(be0/xs1) @ B1^T ----------------
__global__ __launch_bounds__(256) void k_be1(const float* __restrict__ B1){
  __shared__ float xn[16][HID];
  __shared__ float sxs[16];
  int tid=threadIdx.x;
  int row0=blockIdx.x*16;
  if (tid<16) sxs[tid]=g_xs1[row0+tid];
  __syncthreads();
  for (int i=tid;i<16*HID;i+=256){
    int r=i>>9;
    float v = g_be0[row0*HID + i]/sxs[r];
    xn[r][i&511] = fminf(fmaxf(v,-1.f),1.f);
  }
  __syncthreads();
  int n0=tid, n1=tid+256;
  float a0[16], a1_[16];
  #pragma unroll
  for (int r=0;r<16;r++){ a0[r]=0.f; a1_[r]=0.f; }
  for (int k=0;k<HID;k+=4){
    float4 w0 = *(const float4*)&B1[n0*HID+k];
    float4 w1 = *(const float4*)&B1[n1*HID+k];
    #pragma unroll
    for (int r=0;r<16;r++){
      float4 x = *(const float4*)&xn[r][k];
      a0 [r] += w0.x*x.x + w0.y*x.y + w0.z*x.z + w0.w*x.w;
      a1_[r] += w1.x*x.x + w1.y*x.y + w1.z*x.z + w1.w*x.w;
    }
  }
  #pragma unroll
  for (int r=0;r<16;r++){
    g_be1[(row0+r)*HID+n0]=a0[r];
    g_be1[(row0+r)*HID+n1]=a1_[r];
  }
}

// ---------------- serial recurrence: 8 clusters x 8 CTAs, BPC=2, f32x2 FFMA -------
// CTA `rank` owns rows [rank*64, rank*64+64). Weights bf16 in smem; x vectors
// planar [2][512] fp32, exchanged by DSMEM push. Thread = (rg 0..15, kq 0..15),
// 4 rows register-tiled per thread; k paired for fma.rn.f32x2.
__device__ __forceinline__ void dot2(const uint8_t* __restrict__ wsm,
                                     const float* __restrict__ xP,   // [2][512]
                                     int rg, int kq,
                                     unsigned long long* __restrict__ accA,
                                     unsigned long long* __restrict__ accB){
  const uint8_t* wr = wsm + (unsigned)(rg*4)*WROWB + (unsigned)kq*16u;
  #pragma unroll
  for (int m=0;m<4;m++){
    int c = kq + m*16;                          // 8-element k-chunk index
    ulonglong2 xa0 = *(const ulonglong2*)(xP + c*8);
    ulonglong2 xa1 = *(const ulonglong2*)(xP + c*8 + 4);
    ulonglong2 xb0 = *(const ulonglong2*)(xP + 512 + c*8);
    ulonglong2 xb1 = *(const ulonglong2*)(xP + 512 + c*8 + 4);
    #pragma unroll
    for (int rr=0;rr<4;rr++){
      uint4 w = *(const uint4*)(wr + (unsigned)rr*WROWB + (unsigned)m*256u);
      unsigned long long p0 = bpack(w.x<<16, w.x&0xffff0000u);
      unsigned long long p1 = bpack(w.y<<16, w.y&0xffff0000u);
      unsigned long long p2 = bpack(w.z<<16, w.z&0xffff0000u);
      unsigned long long p3 = bpack(w.w<<16, w.w&0xffff0000u);
      ffma2(accA[rr], p0, xa0.x); ffma2(accB[rr], p0, xb0.x);
      ffma2(accA[rr], p1, xa0.y); ffma2(accB[rr], p1, xb0.y);
      ffma2(accA[rr], p2, xa1.x); ffma2(accB[rr], p2, xb1.x);
      ffma2(accA[rr], p3, xa1.y); ffma2(accB[rr], p3, xb1.y);
    }
  }
}

__global__ __launch_bounds__(256,1) __cluster_dims__(CLN,1,1)
void k_serial(const float* __restrict__ C1, const float* __restrict__ W1,
              const float* __restrict__ a1, const float* __restrict__ tau,
              const float* __restrict__ gam){
  extern __shared__ __align__(16) uint8_t dynsm[];
  uint8_t* wsmC = dynsm;                 // [64][WROWB] bf16
  uint8_t* wsmW = dynsm + WMATB;

  __shared__ __align__(16) float hbufP[BPC][HID];    // planar h   (remote-written)
  __shared__ __align__(16) float ebufP[BPC][HID];    // planar err (remote-written)
  __shared__ __align__(16) float estageP[BPC][64];
  __shared__ __align__(16) float hstageP[BPC][64];
  __shared__ float2 pout2[64];
  __shared__ float narr[BPC][CLN];
  __shared__ float normloc[BPC];
  __shared__ float sa[64];

  const int tid  = threadIdx.x;
  const int rank = blockIdx.x & (CLN-1);
  const int b0   = (blockIdx.x / CLN) * BPC;
  const int rg   = tid >> 4, kq = tid & 15;
  const float tauv = __ldg(&tau[0]), gamv = __ldg(&gam[0]);

  // -------- prologue: convert weight slices fp32 -> bf16 smem --------
  for (int i=tid; i<64*128; i+=256){
    int r=i>>7, q=i&127;
    float4 vc = __ldg((const float4*)&C1[(rank*64+r)*HID + q*4]);
    float4 vw = __ldg((const float4*)&W1[(rank*64+r)*HID + q*4]);
    __nv_bfloat162 c0 = __floats2bfloat162_rn(vc.x, vc.y);
    __nv_bfloat162 c1 = __floats2bfloat162_rn(vc.z, vc.w);
    __nv_bfloat162 w0 = __floats2bfloat162_rn(vw.x, vw.y);
    __nv_bfloat162 w1 = __floats2bfloat162_rn(vw.z, vw.w);
    uint2 uc; uc.x = *(uint32_t*)&c0; uc.y = *(uint32_t*)&c1;
    uint2 uw; uw.x = *(uint32_t*)&w0; uw.y = *(uint32_t*)&w1;
    *(uint2*)(wsmC + (unsigned)r*WROWB + (unsigned)q*8u) = uc;
    *(uint2*)(wsmW + (unsigned)r*WROWB + (unsigned)q*8u) = uw;
  }
  for (int i=tid;i<BPC*HID;i+=256) (&hbufP[0][0])[i]=0.f;
  if (tid<BPC) normloc[tid]=0.f;
  if (tid<64)  sa[tid] = sigm(__ldg(&a1[rank*64+tid]));
  __syncthreads();

  const uint32_t a_ebuf = smem_u32(&ebufP[0][0]);
  const uint32_t a_hbuf = smem_u32(&hbufP[0][0]);
  const uint32_t a_narr = smem_u32(&narr[0][0]);

  const int eb = tid & 1, erow = tid >> 1;             // epilogue mapping (tid<128)
  const int dest = tid >> 5, chunk = tid & 31;         // push mapping (256 threads)
  const int pb = chunk >> 4;
  const uint32_t x_off = (uint32_t)(pb*2048 + rank*256 + (chunk&15)*16);

  for (int t=0;t<TT;t++){
    // prefetch per-step scalars (consumed after the dot loop)
    float xsv=1.f, be0v=0.f, be1v=0.f;
    if (tid<128){
      int bb = b0+eb;
      xsv  = __ldg(&g_xs1[bb*TT+t]);
      be0v = __ldg(&g_be0[(bb*TT+t)*HID + rank*64 + erow]);
      be1v = __ldg(&g_be1[(bb*TT+t)*HID + rank*64 + erow]);
    }

    // ======== phase 1: p = h @ C1^T (own rows), err, norm partial ========
    {
      unsigned long long accA[4]={0,0,0,0}, accB[4]={0,0,0,0};
      dot2(wsmC, &hbufP[0][0], rg, kq, accA, accB);
      float sA[4], sB[4];
      #pragma unroll
      for (int rr=0;rr<4;rr++){ sA[rr]=hsum2(accA[rr]); sB[rr]=hsum2(accB[rr]); }
      #pragma unroll
      for (int off=8; off; off>>=1)
        #pragma unroll
        for (int rr=0;rr<4;rr++){
          sA[rr] += __shfl_down_sync(0xffffffffu, sA[rr], off, 16);
          sB[rr] += __shfl_down_sync(0xffffffffu, sB[rr], off, 16);
        }
      if (kq==0){
        #pragma unroll
        for (int rr=0;rr<4;rr++) pout2[rg*4+rr] = make_float2(sA[rr], sB[rr]);
      }
    }
    __syncthreads();
    if (tid<128){
      float pv = eb ? pout2[erow].y : pout2[erow].x;
      float p = tanhf(pv) * xsv;
      float e = be0v - p;
      estageP[eb][erow] = e;
      float q = e*e;
      #pragma unroll
      for (int off=16; off>=2; off>>=1) q += __shfl_xor_sync(0xffffffffu,q,off);
      if ((tid&31)<2) atomicAdd(&normloc[tid&1], q);
    }
    __syncthreads();
    {
      float4 v = ((const float4*)estageP)[chunk];
      dsmem_st4(a_ebuf + x_off, (uint32_t)dest, v);
      if (tid<16)
        dsmem_st1(a_narr + (uint32_t)(((tid&1)*CLN + rank)*4), (uint32_t)(tid>>1),
                  normloc[tid&1]);
    }
    CLUSTER_SYNC();

    // ======== phase 2: surprise, ee = err @ W1^T, h update ========
    {
      unsigned long long accA[4]={0,0,0,0}, accB[4]={0,0,0,0};
      dot2(wsmW, &ebufP[0][0], rg, kq, accA, accB);
      float sA[4], sB[4];
      #pragma unroll
      for (int rr=0;rr<4;rr++){ sA[rr]=hsum2(accA[rr]); sB[rr]=hsum2(accB[rr]); }
      #pragma unroll
      for (int off=8; off; off>>=1)
        #pragma unroll
        for (int rr=0;rr<4;rr++){
          sA[rr] += __shfl_down_sync(0xffffffffu, sA[rr], off, 16);
          sB[rr] += __shfl_down_sync(0xffffffffu, sB[rr], off, 16);
        }
      if (kq==0){
        #pragma unroll
        for (int rr=0;rr<4;rr++) pout2[rg*4+rr] = make_float2(sA[rr], sB[rr]);
      }
    }
    __syncthreads();
    if (tid<128){
      float n2 = (narr[eb][0]+narr[eb][1])+(narr[eb][2]+narr[eb][3])
               + (narr[eb][4]+narr[eb][5])+(narr[eb][6]+narr[eb][7]);
      float rel = fminf(sqrtf(n2)/xsv, 4.0f);
      float s = sigm((rel - tauv)/gamv);
      float hold = hbufP[eb][rank*64+erow];
      float eev = eb ? pout2[erow].y : pout2[erow].x;
      float ih = 0.2f*hold + 0.6f*be1v + 0.2f*s*eev;
      float g = s*sa[erow];
      float hn = hold*(1.f-g) + tanhf(ih)*g;
      hstageP[eb][erow] = hn;
      g_h1[((b0+eb)*TT+t)*HID + rank*64 + erow] = hn;
    } else if (tid<128+BPC){
      normloc[tid-128]=0.f;                        // reset for next step
    }
    __syncthreads();
    {
      float4 v = ((const float4*)hstageP)[chunk];
      dsmem_st4(a_hbuf + x_off, (uint32_t)dest, v);
    }
    CLUSTER_SYNC();
  }
}

// ---------------- head: out = [h1, be1] @ head_w^T + head_b ----------------
__global__ __launch_bounds__(256) void k_head(const float* __restrict__ hw,
                                              const float* __restrict__ hb,
                                              float* __restrict__ out){
  __shared__ float sh[8*1024];
  __shared__ float sred[4*8*64];
  int tid=threadIdx.x;
  int row0=blockIdx.x*8;
  for (int i=tid;i<8*1024;i+=256){
    int r=i>>10, j=i&1023;
    sh[i] = (j<512)? g_h1[(row0+r)*HID+j] : g_be1[(row0+r)*HID+(j-512)];
  }
  __syncthreads();
  int c=tid&63, q=tid>>6;
  float acc[8];
  #pragma unroll
  for (int r=0;r<8;r++) acc[r]=0.f;
  for (int k=q*256;k<q*256+256;k+=4){
    float4 w = *(const float4*)&hw[c*1024+k];
    #pragma unroll
    for (int r=0;r<8;r++){
      float4 x = *(const float4*)&sh[r*1024+k];
      acc[r] += w.x*x.x + w.y*x.y + w.z*x.z + w.w*x.w;
    }
  }
  #pragma unroll
  for (int r=0;r<8;r++) sred[(q*8+r)*64+c]=acc[r];
  __syncthreads();
  for (int i=tid;i<8*64;i+=256){
    int r=i>>6, cc=i&63;
    out[(row0+r)*NCLS+cc] = sred[r*64+cc] + sred[(8+r)*64+cc]
                          + sred[(16+r)*64+cc] + sred[(24+r)*64+cc] + __ldg(&hb[cc]);
  }
}

// ---------------- launch ----------------
extern "C" void kernel_launch(void* const* d_in, const int* in_sizes, int n_in,
                              void* d_out, int out_size){
  const float* feats=(const float*)d_in[0];
  const float* B0  =(const float*)d_in[2];
  const float* C1  =(const float*)d_in[7];
  const float* B1  =(const float*)d_in[8];
  const float* W1  =(const float*)d_in[9];
  const float* a1  =(const float*)d_in[10];
  const float* tau1=(const float*)d_in[11];
  const float* gam1=(const float*)d_in[12];
  const float* hw  =(const float*)d_in[13];
  const float* hb  =(const float*)d_in[14];
  float* out=(float*)d_out;

  static int smem_set = 0;
  if (!smem_set){
    cudaFuncSetAttribute(k_serial, cudaFuncAttributeMaxDynamicSharedMemorySize, DYNSM);
    smem_set = 1;
  }

  k_be0   <<<NROW/16,256>>>(feats,B0);
  k_be1   <<<NROW/16,256>>>(B1);
  k_serial<<<NCTA,256,DYNSM>>>(C1,W1,a1,tau1,gam1);
  k_head  <<<NROW/8,256>>>(hw,hb,out);
}